// round 11
// baseline (speedup 1.0000x reference)
#include <cuda_runtime.h>
#include <cstdint>

#define NN 100000
#define EE 3200000
#define D_IN 512
#define D_HID 16
#define N_CLS 7

typedef unsigned long long ull;

// Scratch (device globals: allocation-free per harness rules)
__device__ __align__(16) float g_h1[NN * D_HID];     // x @ W1
__device__ __align__(16) float g_agg1[NN * D_HID];   // gather-sum of h1
__device__ __align__(16) float g_h2[NN * 8];         // relu(agg1+b1) @ W2, padded 7->8
__device__ int g_is64;                               // edge-index dtype flag

// CSR scratch (rebuilt every launch: graph replay safe)
__device__ int g_deg[NN];
__device__ int g_part[100352];     // per-element exclusive scan within scan-block
__device__ int g_bsum[256];        // per-scan-block totals
__device__ int g_boff[256];        // exclusive scan of block totals
__device__ int g_off[NN];          // bucket start
__device__ int g_pos[NN];          // running cursor (reorder)
__device__ int g_esrc[EE];         // src ids sorted by dst

#define SCAN_B  512
#define SCAN_NB 196                // 196*512 = 100352 >= NN

// Packed f32x2 FMA helpers
__device__ __forceinline__ void fma2(ull& a, ull x, ull w) {
    asm("fma.rn.f32x2 %0, %1, %2, %0;" : "+l"(a) : "l"(x), "l"(w));
}
__device__ __forceinline__ ull splat2(float f) {
    ull r;
    asm("mov.b64 %0, {%1,%1};" : "=l"(r) : "f"(f));
    return r;
}
__device__ __forceinline__ uint32_t smem_u32(const void* p) {
    uint32_t a;
    asm("{ .reg .u64 t; cvta.to.shared.u64 t, %1; cvt.u32.u64 %0, t; }"
        : "=r"(a) : "l"(p));
    return a;
}
__device__ __forceinline__ void cpa16(uint32_t dst, const void* src) {
    asm volatile("cp.async.cg.shared.global [%0], [%1], 16;" :: "r"(dst), "l"(src));
}
__device__ __forceinline__ void cpa_commit() { asm volatile("cp.async.commit_group;"); }
template <int N>
__device__ __forceinline__ void cpa_wait() {
    asm volatile("cp.async.wait_group %0;" :: "n"(N));
}

// ---------------------------------------------------------------------------
// Init: zero degree counters + edge dtype detect (every launch).
// ---------------------------------------------------------------------------
__global__ void k_init(const int* __restrict__ ei) {
    int i = blockIdx.x * blockDim.x + threadIdx.x;
    if (i == 0) {
        int s = 0;
        #pragma unroll
        for (int t = 1; t < 64; t += 2) s |= ei[t];
        g_is64 = (s == 0) ? 1 : 0;
    }
    if (i < NN) g_deg[i] = 0;
}

// ---------------------------------------------------------------------------
// Histogram of dst degrees.
// ---------------------------------------------------------------------------
__global__ __launch_bounds__(256) void k_hist(const void* __restrict__ ei) {
    int e = blockIdx.x * blockDim.x + threadIdx.x;
    if (e >= EE) return;
    int dst = g_is64 ? (int)((const long long*)ei)[EE + e]
                     : ((const int*)ei)[EE + e];
    if ((unsigned)dst < NN) atomicAdd(&g_deg[dst], 1);
}

// ---------------------------------------------------------------------------
// Exclusive scan over g_deg (3 kernels).
// ---------------------------------------------------------------------------
__global__ __launch_bounds__(SCAN_B) void k_scan_local() {
    __shared__ int s[SCAN_B];
    int tid = threadIdx.x;
    int i = blockIdx.x * SCAN_B + tid;
    int v = (i < NN) ? g_deg[i] : 0;
    s[tid] = v;
    __syncthreads();
    #pragma unroll
    for (int off = 1; off < SCAN_B; off <<= 1) {
        int t = (tid >= off) ? s[tid - off] : 0;
        __syncthreads();
        s[tid] += t;
        __syncthreads();
    }
    g_part[blockIdx.x * SCAN_B + tid] = s[tid] - v;   // exclusive
    if (tid == SCAN_B - 1) g_bsum[blockIdx.x] = s[tid];
}

__global__ __launch_bounds__(256) void k_scan_bsums() {
    __shared__ int s[256];
    int tid = threadIdx.x;
    int v = (tid < SCAN_NB) ? g_bsum[tid] : 0;
    s[tid] = v;
    __syncthreads();
    #pragma unroll
    for (int off = 1; off < 256; off <<= 1) {
        int t = (tid >= off) ? s[tid - off] : 0;
        __syncthreads();
        s[tid] += t;
        __syncthreads();
    }
    g_boff[tid] = s[tid] - v;                         // exclusive
}

__global__ __launch_bounds__(SCAN_B) void k_scan_add() {
    int i = blockIdx.x * SCAN_B + threadIdx.x;
    if (i >= NN) return;
    int off = g_part[i] + g_boff[blockIdx.x];
    g_off[i] = off;
    g_pos[i] = off;
}

// ---------------------------------------------------------------------------
// Reorder: counting-sort src ids by dst bucket.
// ---------------------------------------------------------------------------
__global__ __launch_bounds__(256) void k_reorder(const void* __restrict__ ei) {
    int e = blockIdx.x * blockDim.x + threadIdx.x;
    if (e >= EE) return;
    int src, dst;
    if (g_is64) {
        const long long* p = (const long long*)ei;
        src = (int)p[e];
        dst = (int)p[EE + e];
    } else {
        const int* p = (const int*)ei;
        src = p[e];
        dst = p[EE + e];
    }
    if ((unsigned)src >= NN || (unsigned)dst >= NN) return;
    int pos = atomicAdd(&g_pos[dst], 1);
    g_esrc[pos] = src;
}

// ---------------------------------------------------------------------------
// GEMM1 (x-stationary): thread = node, 16 outputs in 8 packed ull regs.
// x tile double-buffered via cp.async; W1 rows broadcast-LDS.
// ---------------------------------------------------------------------------
#define G1_T   128
#define G1_KC  32
#define G1_NCH (D_IN / G1_KC)
#define G1_XP  36
#define G1_BLOCKS ((NN + G1_T - 1) / G1_T)

__global__ __launch_bounds__(G1_T) void k_gemm1(const float* __restrict__ x,
                                                const float* __restrict__ W1) {
    __shared__ float xs[2][G1_T][G1_XP];
    __shared__ float wsc[2][G1_KC][16];

    int tid = threadIdx.x;
    int nbase = blockIdx.x * G1_T;
    int gn = nbase + tid;

    auto stage = [&](int kc, int b) {
        #pragma unroll
        for (int r = 0; r < 8; r++) {
            int idx = r * G1_T + tid;
            int mm  = idx >> 3;
            int kk4 = (idx & 7) * 4;
            int gm  = nbase + mm;
            if (gm < NN) {
                uint32_t dst = smem_u32(&xs[b][mm][kk4]);
                cpa16(dst, x + (size_t)gm * D_IN + kc * G1_KC + kk4);
            }
        }
        uint32_t dst = smem_u32(&wsc[b][0][0]) + tid * 16;
        cpa16(dst, W1 + kc * (G1_KC * 16) + tid * 4);
    };

    ull acc[8];
    #pragma unroll
    for (int j = 0; j < 8; j++) acc[j] = 0ull;

    stage(0, 0);
    cpa_commit();

    for (int kc = 0; kc < G1_NCH; kc++) {
        int b = kc & 1;
        if (kc < G1_NCH - 1) {
            stage(kc + 1, (kc + 1) & 1);
            cpa_commit();
            cpa_wait<1>();
        } else {
            cpa_wait<0>();
        }
        __syncthreads();

        const float4* xrow = reinterpret_cast<const float4*>(&xs[b][tid][0]);
        #pragma unroll
        for (int g = 0; g < 8; g++) {
            float4 xv = xrow[g];
            #pragma unroll
            for (int s = 0; s < 4; s++) {
                float xf = (s == 0) ? xv.x : (s == 1) ? xv.y : (s == 2) ? xv.z : xv.w;
                ull x2 = splat2(xf);
                const ull* wrow = reinterpret_cast<const ull*>(&wsc[b][g * 4 + s][0]);
                #pragma unroll
                for (int j = 0; j < 8; j++)
                    fma2(acc[j], x2, wrow[j]);
            }
        }
        __syncthreads();
    }

    if (gn < NN) {
        ulonglong2* op = reinterpret_cast<ulonglong2*>(g_h1 + (size_t)gn * 16);
        ulonglong2 v0, v1, v2, v3;
        v0.x = acc[0]; v0.y = acc[1];
        v1.x = acc[2]; v1.y = acc[3];
        v2.x = acc[4]; v2.y = acc[5];
        v3.x = acc[6]; v3.y = acc[7];
        op[0] = v0; op[1] = v1; op[2] = v2; op[3] = v3;
    }
}

// ---------------------------------------------------------------------------
// Gather1: agg1[n] = sum of h1[src] over n's CSR bucket. Warp = node,
// 4 lanes/edge (chunk = lane&3, slot = lane>>2, 8 edges per iteration).
// Register accumulation + shfl reduction, one coalesced 64B store. No atomics.
// ---------------------------------------------------------------------------
__global__ __launch_bounds__(256) void k_gather1() {
    int warpGlobal = (blockIdx.x * 256 + threadIdx.x) >> 5;   // node id
    int lane = threadIdx.x & 31;
    if (warpGlobal >= NN) return;
    int n = warpGlobal;
    int start = g_off[n];
    int deg   = g_deg[n];
    int chunk = lane & 3;
    float4 acc = make_float4(0.f, 0.f, 0.f, 0.f);

    for (int t = lane >> 2; t < deg; t += 8) {
        int src = g_esrc[start + t];
        float4 v = reinterpret_cast<const float4*>(g_h1)[(size_t)src * 4 + chunk];
        acc.x += v.x; acc.y += v.y; acc.z += v.z; acc.w += v.w;
    }
    // Reduce over slots (lanes differing in bits 2,3,4; chunk preserved).
    #pragma unroll
    for (int m = 4; m <= 16; m <<= 1) {
        acc.x += __shfl_xor_sync(0xffffffffu, acc.x, m);
        acc.y += __shfl_xor_sync(0xffffffffu, acc.y, m);
        acc.z += __shfl_xor_sync(0xffffffffu, acc.z, m);
        acc.w += __shfl_xor_sync(0xffffffffu, acc.w, m);
    }
    if (lane < 4)
        reinterpret_cast<float4*>(g_agg1)[(size_t)n * 4 + lane] = acc;
}

// ---------------------------------------------------------------------------
// GEMM2: g_h2 = relu(agg1 + b1) @ W2  (row padded to 8 floats, last = 0)
// ---------------------------------------------------------------------------
__global__ __launch_bounds__(256) void k_gemm2(const float* __restrict__ b1,
                                               const float* __restrict__ W2) {
    __shared__ float w2s[16 * 7];
    __shared__ float b1s[16];
    if (threadIdx.x < 112) w2s[threadIdx.x] = W2[threadIdx.x];
    if (threadIdx.x < 16)  b1s[threadIdx.x] = b1[threadIdx.x];
    __syncthreads();

    int n = blockIdx.x * blockDim.x + threadIdx.x;
    if (n >= NN) return;

    const float4* ap = reinterpret_cast<const float4*>(g_agg1 + (size_t)n * 16);
    float h[16];
    float4 t0 = ap[0], t1 = ap[1], t2 = ap[2], t3 = ap[3];
    h[0] = t0.x; h[1] = t0.y; h[2]  = t0.z; h[3]  = t0.w;
    h[4] = t1.x; h[5] = t1.y; h[6]  = t1.z; h[7]  = t1.w;
    h[8] = t2.x; h[9] = t2.y; h[10] = t2.z; h[11] = t2.w;
    h[12] = t3.x; h[13] = t3.y; h[14] = t3.z; h[15] = t3.w;
    #pragma unroll
    for (int j = 0; j < 16; j++) h[j] = fmaxf(h[j] + b1s[j], 0.f);

    float o[8];
    #pragma unroll
    for (int c = 0; c < 7; c++) {
        float s = 0.f;
        #pragma unroll
        for (int j = 0; j < 16; j++) s = fmaf(h[j], w2s[j * 7 + c], s);
        o[c] = s;
    }
    o[7] = 0.f;

    float4* op = reinterpret_cast<float4*>(g_h2 + (size_t)n * 8);
    op[0] = make_float4(o[0], o[1], o[2], o[3]);
    op[1] = make_float4(o[4], o[5], o[6], o[7]);
}

// ---------------------------------------------------------------------------
// Gather2: out[n] = sum of h2[src] over n's bucket + b2. Warp = node,
// 2 lanes/edge (chunk = lane&1, 16 edges per iteration). Writes out directly.
// ---------------------------------------------------------------------------
__global__ __launch_bounds__(256) void k_gather2(const float* __restrict__ b2,
                                                 float* __restrict__ out) {
    int warpGlobal = (blockIdx.x * 256 + threadIdx.x) >> 5;   // node id
    int lane = threadIdx.x & 31;
    if (warpGlobal >= NN) return;
    int n = warpGlobal;
    int start = g_off[n];
    int deg   = g_deg[n];
    int chunk = lane & 1;
    float4 acc = make_float4(0.f, 0.f, 0.f, 0.f);

    for (int t = lane >> 1; t < deg; t += 16) {
        int src = g_esrc[start + t];
        float4 v = reinterpret_cast<const float4*>(g_h2)[(size_t)src * 2 + chunk];
        acc.x += v.x; acc.y += v.y; acc.z += v.z; acc.w += v.w;
    }
    // Reduce over slots (lanes differing in bits 1..4; chunk preserved).
    #pragma unroll
    for (int m = 2; m <= 16; m <<= 1) {
        acc.x += __shfl_xor_sync(0xffffffffu, acc.x, m);
        acc.y += __shfl_xor_sync(0xffffffffu, acc.y, m);
        acc.z += __shfl_xor_sync(0xffffffffu, acc.z, m);
        acc.w += __shfl_xor_sync(0xffffffffu, acc.w, m);
    }
    float* op = out + (size_t)n * 7;
    if (lane == 0) {
        op[0] = acc.x + b2[0];
        op[1] = acc.y + b2[1];
        op[2] = acc.z + b2[2];
        op[3] = acc.w + b2[3];
    } else if (lane == 1) {
        op[4] = acc.x + b2[4];
        op[5] = acc.y + b2[5];
        op[6] = acc.z + b2[6];
    }
}

// ---------------------------------------------------------------------------
extern "C" void kernel_launch(void* const* d_in, const int* in_sizes, int n_in,
                              void* d_out, int out_size) {
    // Map inputs by element count (all six are distinct) — immune to ordering.
    const float* x  = nullptr;
    const void*  ei = nullptr;
    const float* W1 = nullptr;
    const float* b1 = nullptr;
    const float* W2 = nullptr;
    const float* b2 = nullptr;
    for (int i = 0; i < n_in; i++) {
        switch (in_sizes[i]) {
            case NN * D_IN:        x  = (const float*)d_in[i]; break;  // 51,200,000
            case 2 * EE:           ei = d_in[i];                break;  // 6,400,000
            case D_IN * D_HID:     W1 = (const float*)d_in[i]; break;  // 8192
            case D_HID:            b1 = (const float*)d_in[i]; break;  // 16
            case D_HID * N_CLS:    W2 = (const float*)d_in[i]; break;  // 112
            case N_CLS:            b2 = (const float*)d_in[i]; break;  // 7
            default: break;
        }
    }
    float* out = (float*)d_out;

    k_init<<<(NN + 255) / 256, 256>>>((const int*)ei);
    k_gemm1<<<G1_BLOCKS, G1_T>>>(x, W1);
    k_hist<<<(EE + 255) / 256, 256>>>(ei);
    k_scan_local<<<SCAN_NB, SCAN_B>>>();
    k_scan_bsums<<<1, 256>>>();
    k_scan_add<<<SCAN_NB, SCAN_B>>>();
    k_reorder<<<(EE + 255) / 256, 256>>>(ei);
    k_gather1<<<(NN * 32 + 255) / 256, 256>>>();
    k_gemm2<<<(NN + 255) / 256, 256>>>(b1, W2);
    k_gather2<<<(NN * 32 + 255) / 256, 256>>>(b2, out);
}